// round 6
// baseline (speedup 1.0000x reference)
#include <cuda_runtime.h>
#include <cstdint>
#include <cstddef>

// Problem constants
#define NTOK 8192          // B*S tokens
#define HD   2048          // hidden
#define NEXP 8             // experts
#define FD   1408          // moe inter dim
#define CAP  8192          // per-expert row capacity (worst case all tokens)

// GEMM tiling
#define AS    36           // smem row stride (32 + 4 pad -> conflict-free frag loads)
#define ABUF  (128 * AS)
#define BBUF  (64 * AS)
#define KT1   (HD / 32)    // 64 k-tiles for gate/up
#define KT2   (FD / 32)    // 44 k-tiles for down
#define SMEM1 ((2 * ABUF + 4 * BBUF) * 4 + 512)
#define SMEM2 ((2 * ABUF + 2 * BBUF) * 4 + 1024)

// Scratch (device globals: allocation-free rule)
__device__ int   g_count[NEXP];
__device__ int   g_slots[NEXP * CAP];            // slot id = token*2 + k
__device__ float g_slot_w[NTOK * 2];
__device__ float g_hbuf[(size_t)NTOK * 2 * FD];  // swiglu output per slot
__device__ float g_sout[(size_t)NTOK * 2 * HD];  // weighted down output per slot

// ---------------------------------------------------------------------------
// helpers
// ---------------------------------------------------------------------------
__device__ __forceinline__ uint32_t to_tf32(float f) {
  uint32_t u;
  asm("cvt.rna.tf32.f32 %0, %1;" : "=r"(u) : "f"(f));
  return u;
}

__device__ __forceinline__ void mma_tf32(float* c, const uint32_t* a, const uint32_t* b) {
  asm volatile(
      "mma.sync.aligned.m16n8k8.row.col.f32.tf32.tf32.f32 "
      "{%0,%1,%2,%3}, {%4,%5,%6,%7}, {%8,%9}, {%0,%1,%2,%3};\n"
      : "+f"(c[0]), "+f"(c[1]), "+f"(c[2]), "+f"(c[3])
      : "r"(a[0]), "r"(a[1]), "r"(a[2]), "r"(a[3]), "r"(b[0]), "r"(b[1]));
}

__device__ __forceinline__ void cp16(void* sdst, const void* gsrc, int src_bytes) {
  uint32_t sa = (uint32_t)__cvta_generic_to_shared(sdst);
  asm volatile("cp.async.cg.shared.global [%0], [%1], 16, %2;\n"
               :: "r"(sa), "l"(gsrc), "r"(src_bytes));
}
__device__ __forceinline__ void cp_commit() {
  asm volatile("cp.async.commit_group;\n");
}

// ---------------------------------------------------------------------------
// 0) zero expert counters
// ---------------------------------------------------------------------------
__global__ void zero_counts_kernel() {
  if (threadIdx.x < NEXP) g_count[threadIdx.x] = 0;
}

// ---------------------------------------------------------------------------
// 1) router: logits (exact fp32), top-2, normalized weights, slot assignment.
//    Atomic ordering only permutes rows within an expert; each row's math is
//    independent and scattered back by slot id -> bit-deterministic output.
// ---------------------------------------------------------------------------
__global__ void __launch_bounds__(256) router_kernel(
    const float* __restrict__ x, const float* __restrict__ rw) {
  __shared__ float4 xs[HD / 4];
  __shared__ float logits[NEXP];
  const int t = blockIdx.x;
  const float4* xr = (const float4*)(x + (size_t)t * HD);
  for (int i = threadIdx.x; i < HD / 4; i += 256) xs[i] = xr[i];
  __syncthreads();
  const int w = threadIdx.x >> 5, lane = threadIdx.x & 31;
  const float4* rw4 = (const float4*)(rw + w * HD);
  float acc = 0.f;
  for (int i = lane; i < HD / 4; i += 32) {
    float4 a = xs[i], b = rw4[i];
    acc += a.x * b.x + a.y * b.y + a.z * b.z + a.w * b.w;
  }
  #pragma unroll
  for (int off = 16; off > 0; off >>= 1) acc += __shfl_xor_sync(0xffffffffu, acc, off);
  if (lane == 0) logits[w] = acc;
  __syncthreads();
  if (threadIdx.x == 0) {
    int e0 = 0; float l0 = logits[0];
    #pragma unroll
    for (int e = 1; e < NEXP; e++) if (logits[e] > l0) { l0 = logits[e]; e0 = e; }
    int e1 = -1; float l1 = -3.4e38f;
    #pragma unroll
    for (int e = 0; e < NEXP; e++) if (e != e0 && logits[e] > l1) { l1 = logits[e]; e1 = e; }
    // topk(softmax) renormalized == 2-way softmax over the top-2 logits
    float p1 = __expf(l1 - l0);      // l0 >= l1
    float inv = 1.f / (1.f + p1);
    int pos0 = atomicAdd(&g_count[e0], 1);
    g_slots[e0 * CAP + pos0] = 2 * t;
    g_slot_w[2 * t] = inv;
    int pos1 = atomicAdd(&g_count[e1], 1);
    g_slots[e1 * CAP + pos1] = 2 * t + 1;
    g_slot_w[2 * t + 1] = p1 * inv;
  }
}

// ---------------------------------------------------------------------------
// 2) fused gate+up GEMM + SwiGLU.  C[128 x 64] per block, tf32 mma,
//    cp.async double-buffered, A rows gathered indirectly by token id.
// ---------------------------------------------------------------------------
__global__ void __launch_bounds__(256) gemm_gateup_kernel(
    const float* __restrict__ x,
    const float* __restrict__ gate_w,
    const float* __restrict__ up_w) {
  const int e = blockIdx.z;
  const int Ne = g_count[e];
  const int bm = blockIdx.y;
  if (bm * 128 >= Ne) return;
  const int bn = blockIdx.x;
  const int tid = threadIdx.x;

  extern __shared__ float sm[];
  float* Asm = sm;
  float* Bgm = sm + 2 * ABUF;
  float* Bum = Bgm + 2 * BBUF;
  int* slots = (int*)(Bum + 2 * BBUF);

  if (tid < 128) {
    int gr = bm * 128 + tid;
    slots[tid] = (gr < Ne) ? g_slots[e * CAP + gr] : -1;
  }
  __syncthreads();

  const int ar = tid >> 1;
  const int aj = (tid & 1) * 16;
  const int s_a = slots[ar];
  const float* gA = x + (size_t)((s_a >= 0) ? (s_a >> 1) : 0) * HD + aj;
  const int a_sz = (s_a >= 0) ? 16 : 0;
  const size_t wb = (size_t)e * FD * HD;

  const int wid = tid >> 5, lane = tid & 31;
  const int wm = wid & 3, wn = wid >> 2;
  const int lr = lane >> 2, lc = lane & 3;

  float cg[2][4][4], cu[2][4][4];
  #pragma unroll
  for (int i = 0; i < 2; i++)
    #pragma unroll
    for (int j = 0; j < 4; j++)
      #pragma unroll
      for (int q = 0; q < 4; q++) { cg[i][j][q] = 0.f; cu[i][j][q] = 0.f; }

  auto load_tile = [&](int kt, int buf) {
    const int k0 = kt * 32;
    float* dA = Asm + buf * ABUF + ar * AS + aj;
    const float* srcA = gA + k0;
    cp16(dA,      srcA,      a_sz);
    cp16(dA + 4,  srcA + 4,  a_sz);
    cp16(dA + 8,  srcA + 8,  a_sz);
    cp16(dA + 12, srcA + 12, a_sz);
    #pragma unroll
    for (int r2 = 0; r2 < 2; r2++) {
      int idx = tid * 2 + r2;
      int br = idx >> 3;
      int jj = (idx & 7) * 4;
      size_t go = wb + (size_t)(bn * 64 + br) * HD + k0 + jj;
      cp16(Bgm + buf * BBUF + br * AS + jj, gate_w + go, 16);
      cp16(Bum + buf * BBUF + br * AS + jj, up_w + go, 16);
    }
    cp_commit();
  };

  auto compute_tile = [&](int buf) {
    const float* Ab = Asm + buf * ABUF;
    const float* Gb = Bgm + buf * BBUF;
    const float* Ub = Bum + buf * BBUF;
    #pragma unroll
    for (int ks = 0; ks < 4; ks++) {
      const int kb = ks * 8 + lc;
      uint32_t af[2][4];
      #pragma unroll
      for (int i = 0; i < 2; i++) {
        const int r = wm * 32 + i * 16 + lr;
        af[i][0] = to_tf32(Ab[r * AS + kb]);
        af[i][1] = to_tf32(Ab[(r + 8) * AS + kb]);
        af[i][2] = to_tf32(Ab[r * AS + kb + 4]);
        af[i][3] = to_tf32(Ab[(r + 8) * AS + kb + 4]);
      }
      uint32_t bg[4][2], bu[4][2];
      #pragma unroll
      for (int j = 0; j < 4; j++) {
        const int n = wn * 32 + j * 8 + lr;
        bg[j][0] = to_tf32(Gb[n * AS + kb]);
        bg[j][1] = to_tf32(Gb[n * AS + kb + 4]);
        bu[j][0] = to_tf32(Ub[n * AS + kb]);
        bu[j][1] = to_tf32(Ub[n * AS + kb + 4]);
      }
      #pragma unroll
      for (int i = 0; i < 2; i++)
        #pragma unroll
        for (int j = 0; j < 4; j++) {
          mma_tf32(cg[i][j], af[i], bg[j]);
          mma_tf32(cu[i][j], af[i], bu[j]);
        }
    }
  };

  load_tile(0, 0);
  #pragma unroll 1
  for (int kt = 0; kt < KT1; kt++) {
    const int buf = kt & 1;
    if (kt + 1 < KT1) {
      load_tile(kt + 1, buf ^ 1);
      asm volatile("cp.async.wait_group 1;\n");
    } else {
      asm volatile("cp.async.wait_group 0;\n");
    }
    __syncthreads();
    compute_tile(buf);
    __syncthreads();
  }

  // SwiGLU epilogue -> hbuf[slot][F]
  #pragma unroll
  for (int i = 0; i < 2; i++)
    #pragma unroll
    for (int h = 0; h < 2; h++) {
      const int r = wm * 32 + i * 16 + h * 8 + lr;
      const int s = slots[r];
      if (s < 0) continue;
      float* orow = g_hbuf + (size_t)s * FD + bn * 64 + wn * 32 + lc * 2;
      #pragma unroll
      for (int j = 0; j < 4; j++) {
        float g0 = cg[i][j][h * 2], g1 = cg[i][j][h * 2 + 1];
        float u0 = cu[i][j][h * 2], u1 = cu[i][j][h * 2 + 1];
        float v0 = g0 * u0 / (1.f + __expf(-g0));
        float v1 = g1 * u1 / (1.f + __expf(-g1));
        *(float2*)(orow + j * 8) = make_float2(v0, v1);
      }
    }
}

// ---------------------------------------------------------------------------
// 3) down GEMM: sout[slot][H] = weight * (hbuf[slot] @ down_w[e]^T)
// ---------------------------------------------------------------------------
__global__ void __launch_bounds__(256) gemm_down_kernel(
    const float* __restrict__ down_w) {
  const int e = blockIdx.z;
  const int Ne = g_count[e];
  const int bm = blockIdx.y;
  if (bm * 128 >= Ne) return;
  const int bn = blockIdx.x;
  const int tid = threadIdx.x;

  extern __shared__ float sm[];
  float* Asm = sm;
  float* Bdm = sm + 2 * ABUF;
  int* slots = (int*)(Bdm + 2 * BBUF);
  float* wts = (float*)(slots + 128);

  if (tid < 128) {
    int gr = bm * 128 + tid;
    int s = (gr < Ne) ? g_slots[e * CAP + gr] : -1;
    slots[tid] = s;
    wts[tid] = (s >= 0) ? g_slot_w[s] : 0.f;
  }
  __syncthreads();

  const int ar = tid >> 1;
  const int aj = (tid & 1) * 16;
  const int s_a = slots[ar];
  const float* gA = g_hbuf + (size_t)((s_a >= 0) ? s_a : 0) * FD + aj;
  const int a_sz = (s_a >= 0) ? 16 : 0;
  const size_t wb = (size_t)e * HD * FD;

  const int wid = tid >> 5, lane = tid & 31;
  const int wm = wid & 3, wn = wid >> 2;
  const int lr = lane >> 2, lc = lane & 3;

  float cd[2][4][4];
  #pragma unroll
  for (int i = 0; i < 2; i++)
    #pragma unroll
    for (int j = 0; j < 4; j++)
      #pragma unroll
      for (int q = 0; q < 4; q++) cd[i][j][q] = 0.f;

  auto load_tile = [&](int kt, int buf) {
    const int k0 = kt * 32;
    float* dA = Asm + buf * ABUF + ar * AS + aj;
    const float* srcA = gA + k0;
    cp16(dA,      srcA,      a_sz);
    cp16(dA + 4,  srcA + 4,  a_sz);
    cp16(dA + 8,  srcA + 8,  a_sz);
    cp16(dA + 12, srcA + 12, a_sz);
    #pragma unroll
    for (int r2 = 0; r2 < 2; r2++) {
      int idx = tid * 2 + r2;
      int br = idx >> 3;
      int jj = (idx & 7) * 4;
      cp16(Bdm + buf * BBUF + br * AS + jj,
           down_w + wb + (size_t)(bn * 64 + br) * FD + k0 + jj, 16);
    }
    cp_commit();
  };

  auto compute_tile = [&](int buf) {
    const float* Ab = Asm + buf * ABUF;
    const float* Db = Bdm + buf * BBUF;
    #pragma unroll
    for (int ks = 0; ks < 4; ks++) {
      const int kb = ks * 8 + lc;
      uint32_t af[2][4];
      #pragma unroll
      for (int i = 0; i < 2; i++) {
        const int r = wm * 32 + i * 16 + lr;
        af[i][0] = to_tf32(Ab[r * AS + kb]);
        af[i][1] = to_tf32(Ab[(r + 8) * AS + kb]);
        af[i][2] = to_tf32(Ab[r * AS + kb + 4]);
        af[i][3] = to_tf32(Ab[(r + 8) * AS + kb + 4]);
      }
      uint32_t bd[4][2];
      #pragma unroll
      for (int j = 0; j < 4; j++) {
        const int n = wn * 32 + j * 8 + lr;
        bd[j][0] = to_tf32(Db[n * AS + kb]);
        bd[j][1] = to_tf32(Db[n * AS + kb + 4]);
      }
      #pragma unroll
      for (int i = 0; i < 2; i++)
        #pragma unroll
        for (int j = 0; j < 4; j++)
          mma_tf32(cd[i][j], af[i], bd[j]);
    }
  };

  load_tile(0, 0);
  #pragma unroll 1
  for (int kt = 0; kt < KT2; kt++) {
    const int buf = kt & 1;
    if (kt + 1 < KT2) {
      load_tile(kt + 1, buf ^ 1);
      asm volatile("cp.async.wait_group 1;\n");
    } else {
      asm volatile("cp.async.wait_group 0;\n");
    }
    __syncthreads();
    compute_tile(buf);
    __syncthreads();
  }

  #pragma unroll
  for (int i = 0; i < 2; i++)
    #pragma unroll
    for (int h = 0; h < 2; h++) {
      const int r = wm * 32 + i * 16 + h * 8 + lr;
      const int s = slots[r];
      if (s < 0) continue;
      const float wgt = wts[r];
      float* orow = g_sout + (size_t)s * HD + bn * 64 + wn * 32 + lc * 2;
      #pragma unroll
      for (int j = 0; j < 4; j++) {
        float v0 = cd[i][j][h * 2] * wgt;
        float v1 = cd[i][j][h * 2 + 1] * wgt;
        *(float2*)(orow + j * 8) = make_float2(v0, v1);
      }
    }
}

// ---------------------------------------------------------------------------
// 4) deterministic combine: out[t] = sout[2t] + sout[2t+1]
// ---------------------------------------------------------------------------
__global__ void __launch_bounds__(256) combine_kernel(float* __restrict__ out) {
  const int idx = blockIdx.x * 256 + threadIdx.x;   // float4 index
  const int t = idx >> 9;                           // HD/4 = 512
  const int h4 = idx & 511;
  const float4* s4 = (const float4*)g_sout;
  float4 a = s4[(size_t)(2 * t) * 512 + h4];
  float4 b = s4[(size_t)(2 * t + 1) * 512 + h4];
  ((float4*)out)[idx] = make_float4(a.x + b.x, a.y + b.y, a.z + b.z, a.w + b.w);
}

// ---------------------------------------------------------------------------
extern "C" void kernel_launch(void* const* d_in, const int* in_sizes, int n_in,
                              void* d_out, int out_size) {
  const float* x  = (const float*)d_in[0];  // hidden_states [4,2048,2048]
  const float* rw = (const float*)d_in[1];  // router_w [8,2048]
  const float* gw = (const float*)d_in[2];  // gate_w [8,1408,2048]
  const float* uw = (const float*)d_in[3];  // up_w   [8,1408,2048]
  const float* dw = (const float*)d_in[4];  // down_w [8,2048,1408]
  float* out = (float*)d_out;

  cudaFuncSetAttribute(gemm_gateup_kernel,
                       cudaFuncAttributeMaxDynamicSharedMemorySize, SMEM1);
  cudaFuncSetAttribute(gemm_down_kernel,
                       cudaFuncAttributeMaxDynamicSharedMemorySize, SMEM2);

  zero_counts_kernel<<<1, 32>>>();
  router_kernel<<<NTOK, 256>>>(x, rw);
  gemm_gateup_kernel<<<dim3(FD / 64, CAP / 128, NEXP), 256, SMEM1>>>(x, gw, uw);
  gemm_down_kernel<<<dim3(HD / 64, CAP / 128, NEXP), 256, SMEM2>>>(dw);
  combine_kernel<<<(NTOK * (HD / 4)) / 256, 256>>>(out);
}

// round 14
// speedup vs baseline: 1.0668x; 1.0668x over previous
#include <cuda_runtime.h>
#include <cstdint>
#include <cstddef>

// Problem constants
#define NTOK 8192          // B*S tokens
#define HD   2048          // hidden
#define NEXP 8             // experts
#define FD   1408          // moe inter dim
#define CAP  8192          // per-expert row capacity

#define KT1  (HD / 32)     // 64 k-stages for gate/up
#define KT2  (FD / 32)     // 44 k-stages for down

// smem geometry: rows of 32 floats stored with stride 40 (160B) ->
// phase-disjoint banks for LDS.64 fragment loads (8 rows x 4 pair-cols)
#define AS      40
#define ATILE   (128 * AS)         // 5120 floats
#define BTILE_G (64 * AS)          // 2560 floats (gate/up B tiles)
#define BTILE_D (128 * AS)         // 5120 floats (down B tile)

// gateup smem: A[2], Bg[2], Bu[2], slots
#define GU_A(buf)   ((buf) * ATILE)
#define GU_G(buf)   (2 * ATILE + (buf) * BTILE_G)
#define GU_U(buf)   (2 * ATILE + 2 * BTILE_G + (buf) * BTILE_G)
#define GU_SLOTS    (2 * ATILE + 4 * BTILE_G)            // float idx
#define SMEM_GU     ((GU_SLOTS + 128) * 4)

// down smem: A[2], B[2], slots, wts
#define DN_A(buf)   ((buf) * ATILE)
#define DN_B(buf)   (2 * ATILE + (buf) * BTILE_D)
#define DN_SLOTS    (2 * ATILE + 2 * BTILE_D)
#define SMEM_DN     ((DN_SLOTS + 256) * 4)

// Scratch (device globals: allocation-free rule)
__device__ int   g_count[NEXP];
__device__ int   g_slots[NEXP * CAP];            // slot id = token*2 + k
__device__ float g_slot_w[NTOK * 2];
__device__ float g_xr[(size_t)NTOK * HD];        // rna-rounded + k-permuted x
__device__ float g_gw[(size_t)NEXP * FD * HD];   // rounded+permuted gate_w
__device__ float g_uw[(size_t)NEXP * FD * HD];   // rounded+permuted up_w
__device__ float g_dw[(size_t)NEXP * HD * FD];   // rounded+permuted down_w
__device__ float g_hbuf[(size_t)NTOK * 2 * FD];  // swiglu out (rounded+permuted)
__device__ float g_sout[(size_t)NTOK * 2 * HD];  // weighted down out per slot

// ---------------------------------------------------------------------------
// helpers
// ---------------------------------------------------------------------------
__device__ __forceinline__ uint32_t to_tf32(float f) {
  uint32_t u;
  asm("cvt.rna.tf32.f32 %0, %1;" : "=r"(u) : "f"(f));
  return u;
}
__device__ __forceinline__ float round_tf32(float f) {
  return __uint_as_float(to_tf32(f));
}

__device__ __forceinline__ void mma_tf32(float* c, const uint32_t* a, const uint32_t* b) {
  asm volatile(
      "mma.sync.aligned.m16n8k8.row.col.f32.tf32.tf32.f32 "
      "{%0,%1,%2,%3}, {%4,%5,%6,%7}, {%8,%9}, {%0,%1,%2,%3};\n"
      : "+f"(c[0]), "+f"(c[1]), "+f"(c[2]), "+f"(c[3])
      : "r"(a[0]), "r"(a[1]), "r"(a[2]), "r"(a[3]), "r"(b[0]), "r"(b[1]));
}

__device__ __forceinline__ void cp16(void* sdst, const void* gsrc, int src_bytes) {
  uint32_t sa = (uint32_t)__cvta_generic_to_shared(sdst);
  asm volatile("cp.async.cg.shared.global [%0], [%1], 16, %2;\n"
               :: "r"(sa), "l"(gsrc), "r"(src_bytes));
}
__device__ __forceinline__ void cp_commit() {
  asm volatile("cp.async.commit_group;\n");
}

// ---------------------------------------------------------------------------
// 0) zero expert counters
// ---------------------------------------------------------------------------
__global__ void zero_counts_kernel() {
  if (threadIdx.x < NEXP) g_count[threadIdx.x] = 0;
}

// ---------------------------------------------------------------------------
// 0b) rna-round to tf32 + k-pair permute: every 8-float group is rewritten
//     as [k0,k4,k1,k5,k2,k6,k3,k7], so an mma fragment's (k, k+4) register
//     pair is contiguous 8 bytes in memory (and in smem after cp.async).
//     All row lengths (HD=2048, FD=1408) are multiples of 8.
// ---------------------------------------------------------------------------
__global__ void __launch_bounds__(256) round_perm_kernel(
    const float4* __restrict__ src, float4* __restrict__ dst, int n8) {
  int i = blockIdx.x * 256 + threadIdx.x;
  if (i >= n8) return;
  float4 v0 = src[2 * i], v1 = src[2 * i + 1];
  float4 o0, o1;
  o0.x = round_tf32(v0.x); o0.y = round_tf32(v1.x);
  o0.z = round_tf32(v0.y); o0.w = round_tf32(v1.y);
  o1.x = round_tf32(v0.z); o1.y = round_tf32(v1.z);
  o1.z = round_tf32(v0.w); o1.w = round_tf32(v1.w);
  dst[2 * i] = o0;
  dst[2 * i + 1] = o1;
}

// ---------------------------------------------------------------------------
// 1) router (exact fp32, raw x): top-2 softmax weights + slot assignment.
//    Atomic ordering only permutes rows within an expert; each row's math is
//    independent and scattered by slot id -> bit-deterministic output.
// ---------------------------------------------------------------------------
__global__ void __launch_bounds__(256) router_kernel(
    const float* __restrict__ x, const float* __restrict__ rw) {
  __shared__ float4 xs[HD / 4];
  __shared__ float logits[NEXP];
  const int t = blockIdx.x;
  const float4* xr = (const float4*)(x + (size_t)t * HD);
  for (int i = threadIdx.x; i < HD / 4; i += 256) xs[i] = xr[i];
  __syncthreads();
  const int w = threadIdx.x >> 5, lane = threadIdx.x & 31;
  const float4* rw4 = (const float4*)(rw + w * HD);
  float acc = 0.f;
  for (int i = lane; i < HD / 4; i += 32) {
    float4 a = xs[i], b = rw4[i];
    acc += a.x * b.x + a.y * b.y + a.z * b.z + a.w * b.w;
  }
  #pragma unroll
  for (int off = 16; off > 0; off >>= 1) acc += __shfl_xor_sync(0xffffffffu, acc, off);
  if (lane == 0) logits[w] = acc;
  __syncthreads();
  if (threadIdx.x == 0) {
    int e0 = 0; float l0 = logits[0];
    #pragma unroll
    for (int e = 1; e < NEXP; e++) if (logits[e] > l0) { l0 = logits[e]; e0 = e; }
    int e1 = -1; float l1 = -3.4e38f;
    #pragma unroll
    for (int e = 0; e < NEXP; e++) if (e != e0 && logits[e] > l1) { l1 = logits[e]; e1 = e; }
    float p1 = __expf(l1 - l0);      // l0 >= l1
    float inv = 1.f / (1.f + p1);
    int pos0 = atomicAdd(&g_count[e0], 1);
    g_slots[e0 * CAP + pos0] = 2 * t;
    g_slot_w[2 * t] = inv;
    int pos1 = atomicAdd(&g_count[e1], 1);
    g_slots[e1 * CAP + pos1] = 2 * t + 1;
    g_slot_w[2 * t + 1] = p1 * inv;
  }
}

// ---------------------------------------------------------------------------
// 2) fused gate+up GEMM + SwiGLU.  C[128 x 64] per block (dual-mat),
//    tf32 mma with LDS.64 paired fragment loads (pre-permuted inputs, no cvt).
// ---------------------------------------------------------------------------
__global__ void __launch_bounds__(256, 2) gemm_gateup_kernel(
    const float* __restrict__ x,
    const float* __restrict__ gate_w,
    const float* __restrict__ up_w) {
  const int e = blockIdx.z;
  const int Ne = g_count[e];
  const int bm = blockIdx.y;
  if (bm * 128 >= Ne) return;
  const int bn = blockIdx.x;
  const int tid = threadIdx.x;

  extern __shared__ float sm[];
  int* slots = (int*)(sm + GU_SLOTS);

  if (tid < 128) {
    int gr = bm * 128 + tid;
    slots[tid] = (gr < Ne) ? g_slots[e * CAP + gr] : -1;
  }
  __syncthreads();

  // producer mapping
  const int ar = tid >> 1;                 // A row 0..127
  const int ah = (tid & 1) * 16;           // half-row (16 floats = 64B)
  const int s_a = slots[ar];
  const float* gA = x + (size_t)((s_a >= 0) ? (s_a >> 1) : 0) * HD + ah;
  const int a_sz = (s_a >= 0) ? 16 : 0;
  const int br = tid >> 2;                 // B row 0..63
  const int bq = (tid & 3) * 8;            // quarter-row (8 floats = 32B)
  const size_t wbase = (size_t)e * FD * HD;
  const float* gG = gate_w + wbase + (size_t)(bn * 64 + br) * HD + bq;
  const float* gU = up_w   + wbase + (size_t)(bn * 64 + br) * HD + bq;

  const int wid = tid >> 5, lane = tid & 31;
  const int wm = wid & 3, wn = wid >> 2;
  const int lr = lane >> 2, lc = lane & 3;

  float cg[2][4][4], cu[2][4][4];
  #pragma unroll
  for (int i = 0; i < 2; i++)
    #pragma unroll
    for (int j = 0; j < 4; j++)
      #pragma unroll
      for (int q = 0; q < 4; q++) { cg[i][j][q] = 0.f; cu[i][j][q] = 0.f; }

  auto load_stage = [&](int kt, int buf) {
    const int k0 = kt * 32;
    float* dA = sm + GU_A(buf) + ar * AS + ah;
    const float* sA = gA + k0;
    cp16(dA,      sA,      a_sz);
    cp16(dA + 4,  sA + 4,  a_sz);
    cp16(dA + 8,  sA + 8,  a_sz);
    cp16(dA + 12, sA + 12, a_sz);
    float* dG = sm + GU_G(buf) + br * AS + bq;
    float* dU = sm + GU_U(buf) + br * AS + bq;
    cp16(dG,     gG + k0,     16);
    cp16(dG + 4, gG + k0 + 4, 16);
    cp16(dU,     gU + k0,     16);
    cp16(dU + 4, gU + k0 + 4, 16);
    cp_commit();
  };

  auto compute_stage = [&](int buf) {
    const float* Ab = sm + GU_A(buf);
    const float* Gb = sm + GU_G(buf);
    const float* Ub = sm + GU_U(buf);
    #pragma unroll
    for (int ks = 0; ks < 4; ks++) {
      const int co = ks * 8 + lc * 2;      // permuted pair (k, k+4)
      uint32_t af[2][4];
      #pragma unroll
      for (int i = 0; i < 2; i++) {
        const int r = wm * 32 + i * 16 + lr;
        float2 lo = *(const float2*)(Ab + r * AS + co);
        float2 hi = *(const float2*)(Ab + (r + 8) * AS + co);
        af[i][0] = __float_as_uint(lo.x);
        af[i][1] = __float_as_uint(hi.x);
        af[i][2] = __float_as_uint(lo.y);
        af[i][3] = __float_as_uint(hi.y);
      }
      uint32_t bg[4][2], bu[4][2];
      #pragma unroll
      for (int j = 0; j < 4; j++) {
        const int n = wn * 32 + j * 8 + lr;
        float2 g = *(const float2*)(Gb + n * AS + co);
        float2 u = *(const float2*)(Ub + n * AS + co);
        bg[j][0] = __float_as_uint(g.x); bg[j][1] = __float_as_uint(g.y);
        bu[j][0] = __float_as_uint(u.x); bu[j][1] = __float_as_uint(u.y);
      }
      #pragma unroll
      for (int i = 0; i < 2; i++)
        #pragma unroll
        for (int j = 0; j < 4; j++) {
          mma_tf32(cg[i][j], af[i], bg[j]);
          mma_tf32(cu[i][j], af[i], bu[j]);
        }
    }
  };

  load_stage(0, 0);
  #pragma unroll 1
  for (int kt = 0; kt < KT1; kt++) {
    const int buf = kt & 1;
    if (kt + 1 < KT1) {
      load_stage(kt + 1, buf ^ 1);
      asm volatile("cp.async.wait_group 1;\n");
    } else {
      asm volatile("cp.async.wait_group 0;\n");
    }
    __syncthreads();
    compute_stage(buf);
    __syncthreads();
  }

  // SwiGLU epilogue -> hbuf[slot][F], stored ROUNDED + K-PERMUTED
  // cols (2lc, 2lc+1) land at permuted positions (pos0, pos0+2)
  const int pos0 = ((lc & 1) << 2) | (lc >> 1);    // 0,4,1,5
  #pragma unroll
  for (int i = 0; i < 2; i++)
    #pragma unroll
    for (int h = 0; h < 2; h++) {
      const int r = wm * 32 + i * 16 + h * 8 + lr;
      const int s = slots[r];
      if (s < 0) continue;
      float* orow = g_hbuf + (size_t)s * FD + bn * 64 + wn * 32;
      #pragma unroll
      for (int j = 0; j < 4; j++) {
        float g0 = cg[i][j][h * 2], g1 = cg[i][j][h * 2 + 1];
        float u0 = cu[i][j][h * 2], u1 = cu[i][j][h * 2 + 1];
        float v0 = g0 * u0 / (1.f + __expf(-g0));
        float v1 = g1 * u1 / (1.f + __expf(-g1));
        orow[j * 8 + pos0]     = round_tf32(v0);
        orow[j * 8 + pos0 + 2] = round_tf32(v1);
      }
    }
}

// ---------------------------------------------------------------------------
// 3) down GEMM: sout[slot][H] = weight * (hbuf[slot] @ down_w[e]^T)
//    CTA tile 128 x 128 (warp n = 64), LDS.64 paired loads, no cvt.
// ---------------------------------------------------------------------------
__global__ void __launch_bounds__(256, 2) gemm_down_kernel(
    const float* __restrict__ down_w) {
  const int e = blockIdx.z;
  const int Ne = g_count[e];
  const int bm = blockIdx.y;
  if (bm * 128 >= Ne) return;
  const int bn = blockIdx.x;
  const int tid = threadIdx.x;

  extern __shared__ float sm[];
  int* slots = (int*)(sm + DN_SLOTS);
  float* wts = (float*)(slots + 128);

  if (tid < 128) {
    int gr = bm * 128 + tid;
    int s = (gr < Ne) ? g_slots[e * CAP + gr] : -1;
    slots[tid] = s;
    wts[tid] = (s >= 0) ? g_slot_w[s] : 0.f;
  }
  __syncthreads();

  const int ar = tid >> 1;
  const int ah = (tid & 1) * 16;
  const int s_a = slots[ar];
  const float* gA = g_hbuf + (size_t)((s_a >= 0) ? s_a : 0) * FD + ah;
  const int a_sz = (s_a >= 0) ? 16 : 0;
  const size_t wbase = (size_t)e * HD * FD;
  const float* gB = down_w + wbase + (size_t)(bn * 128 + ar) * FD + ah;

  const int wid = tid >> 5, lane = tid & 31;
  const int wm = wid & 3, wn = wid >> 2;
  const int lr = lane >> 2, lc = lane & 3;

  float cd[2][8][4];
  #pragma unroll
  for (int i = 0; i < 2; i++)
    #pragma unroll
    for (int j = 0; j < 8; j++)
      #pragma unroll
      for (int q = 0; q < 4; q++) cd[i][j][q] = 0.f;

  auto load_stage = [&](int kt, int buf) {
    const int k0 = kt * 32;
    float* dA = sm + DN_A(buf) + ar * AS + ah;
    const float* sA = gA + k0;
    cp16(dA,      sA,      a_sz);
    cp16(dA + 4,  sA + 4,  a_sz);
    cp16(dA + 8,  sA + 8,  a_sz);
    cp16(dA + 12, sA + 12, a_sz);
    float* dB = sm + DN_B(buf) + ar * AS + ah;
    const float* sB = gB + k0;
    cp16(dB,      sB,      16);
    cp16(dB + 4,  sB + 4,  16);
    cp16(dB + 8,  sB + 8,  16);
    cp16(dB + 12, sB + 12, 16);
    cp_commit();
  };

  auto compute_stage = [&](int buf) {
    const float* Ab = sm + DN_A(buf);
    const float* Bb = sm + DN_B(buf);
    #pragma unroll
    for (int ks = 0; ks < 4; ks++) {
      const int co = ks * 8 + lc * 2;
      uint32_t af[2][4];
      #pragma unroll
      for (int i = 0; i < 2; i++) {
        const int r = wm * 32 + i * 16 + lr;
        float2 lo = *(const float2*)(Ab + r * AS + co);
        float2 hi = *(const float2*)(Ab + (r + 8) * AS + co);
        af[i][0] = __float_as_uint(lo.x);
        af[i][1] = __float_as_uint(hi.x);
        af[i][2] = __float_as_uint(lo.y);
        af[i][3] = __float_as_uint(hi.y);
      }
      uint32_t bd[8][2];
      #pragma unroll
      for (int j = 0; j < 8; j++) {
        const int n = wn * 64 + j * 8 + lr;
        float2 b = *(const float2*)(Bb + n * AS + co);
        bd[j][0] = __float_as_uint(b.x);
        bd[j][1] = __float_as_uint(b.y);
      }
      #pragma unroll
      for (int i = 0; i < 2; i++)
        #pragma unroll
        for (int j = 0; j < 8; j++)
          mma_tf32(cd[i][j], af[i], bd[j]);
    }
  };

  load_stage(0, 0);
  #pragma unroll 1
  for (int kt = 0; kt < KT2; kt++) {
    const int buf = kt & 1;
    if (kt + 1 < KT2) {
      load_stage(kt + 1, buf ^ 1);
      asm volatile("cp.async.wait_group 1;\n");
    } else {
      asm volatile("cp.async.wait_group 0;\n");
    }
    __syncthreads();
    compute_stage(buf);
    __syncthreads();
  }

  #pragma unroll
  for (int i = 0; i < 2; i++)
    #pragma unroll
    for (int h = 0; h < 2; h++) {
      const int r = wm * 32 + i * 16 + h * 8 + lr;
      const int s = slots[r];
      if (s < 0) continue;
      const float wgt = wts[r];
      float* orow = g_sout + (size_t)s * HD + bn * 128 + wn * 64 + lc * 2;
      #pragma unroll
      for (int j = 0; j < 8; j++) {
        float v0 = cd[i][j][h * 2] * wgt;
        float v1 = cd[i][j][h * 2 + 1] * wgt;
        *(float2*)(orow + j * 8) = make_float2(v0, v1);
      }
    }
}

// ---------------------------------------------------------------------------
// 4) deterministic combine: out[t] = sout[2t] + sout[2t+1]
// ---------------------------------------------------------------------------
__global__ void __launch_bounds__(256) combine_kernel(float* __restrict__ out) {
  const int idx = blockIdx.x * 256 + threadIdx.x;   // float4 index
  const int t = idx >> 9;                           // HD/4 = 512
  const int h4 = idx & 511;
  const float4* s4 = (const float4*)g_sout;
  float4 a = s4[(size_t)(2 * t) * 512 + h4];
  float4 b = s4[(size_t)(2 * t + 1) * 512 + h4];
  ((float4*)out)[idx] = make_float4(a.x + b.x, a.y + b.y, a.z + b.z, a.w + b.w);
}

// ---------------------------------------------------------------------------
extern "C" void kernel_launch(void* const* d_in, const int* in_sizes, int n_in,
                              void* d_out, int out_size) {
  const float* x  = (const float*)d_in[0];  // hidden_states [4,2048,2048]
  const float* rw = (const float*)d_in[1];  // router_w [8,2048]
  const float* gw = (const float*)d_in[2];  // gate_w [8,1408,2048]
  const float* uw = (const float*)d_in[3];  // up_w   [8,1408,2048]
  const float* dw = (const float*)d_in[4];  // down_w [8,2048,1408]
  float* out = (float*)d_out;

  cudaFuncSetAttribute(gemm_gateup_kernel,
                       cudaFuncAttributeMaxDynamicSharedMemorySize, SMEM_GU);
  cudaFuncSetAttribute(gemm_down_kernel,
                       cudaFuncAttributeMaxDynamicSharedMemorySize, SMEM_DN);

  float* xr_p;  cudaGetSymbolAddress((void**)&xr_p, g_xr);
  float* gw_p;  cudaGetSymbolAddress((void**)&gw_p, g_gw);
  float* uw_p;  cudaGetSymbolAddress((void**)&uw_p, g_uw);
  float* dw_p;  cudaGetSymbolAddress((void**)&dw_p, g_dw);

  const int n8x = NTOK * HD / 8;        // 2,097,152
  const int n8w = NEXP * FD * HD / 8;   // 2,883,584

  zero_counts_kernel<<<1, 32>>>();
  round_perm_kernel<<<(n8x + 255) / 256, 256>>>((const float4*)x,  (float4*)xr_p, n8x);
  round_perm_kernel<<<(n8w + 255) / 256, 256>>>((const float4*)gw, (float4*)gw_p, n8w);
  round_perm_kernel<<<(n8w + 255) / 256, 256>>>((const float4*)uw, (float4*)uw_p, n8w);
  round_perm_kernel<<<(n8w + 255) / 256, 256>>>((const float4*)dw, (float4*)dw_p, n8w);
  router_kernel<<<NTOK, 256>>>(x, rw);
  gemm_gateup_kernel<<<dim3(FD / 64, CAP / 128, NEXP), 256, SMEM_GU>>>(xr_p, gw_p, uw_p);
  gemm_down_kernel<<<dim3(HD / 128, CAP / 128, NEXP), 256, SMEM_DN>>>(dw_p);
  combine_kernel<<<(NTOK * (HD / 4)) / 256, 256>>>(out);
}

// round 15
// speedup vs baseline: 1.5824x; 1.4834x over previous
#include <cuda_runtime.h>
#include <cstdint>
#include <cstddef>

// Problem constants
#define NTOK 8192          // B*S tokens
#define HD   2048          // hidden
#define NEXP 8             // experts
#define FD   1408          // moe inter dim
#define CAP  8192          // per-expert row capacity

#define KT1  (HD / 32)     // 64 k-stages for gate/up
#define KT2  (FD / 32)     // 44 k-stages for down

// smem geometry: rows of 32 floats stored with stride 40 (160B)
#define AS      40
#define ATILE   (128 * AS)         // 5120 floats
#define BTILE   (64 * AS)          // 2560 floats

// gateup smem: A[2], Bg[2], Bu[2], slots
#define GU_A(buf)   ((buf) * ATILE)
#define GU_G(buf)   (2 * ATILE + (buf) * BTILE)
#define GU_U(buf)   (2 * ATILE + 2 * BTILE + (buf) * BTILE)
#define GU_SLOTS    (2 * ATILE + 4 * BTILE)
#define SMEM_GU     ((GU_SLOTS + 128) * 4)

// down smem: A[2], B[2], slots, wts
#define DN_A(buf)   ((buf) * ATILE)
#define DN_B(buf)   (2 * ATILE + (buf) * BTILE)
#define DN_SLOTS    (2 * ATILE + 2 * BTILE)
#define SMEM_DN     ((DN_SLOTS + 256) * 4)

// Scratch (device globals: allocation-free rule)
__device__ int   g_count[NEXP];
__device__ int   g_slots[NEXP * CAP];            // slot id = token*2 + k
__device__ float g_slot_w[NTOK * 2];
__device__ float g_xr[(size_t)NTOK * HD];        // rna-rounded + k-permuted x
__device__ float g_gw[(size_t)NEXP * FD * HD];   // rounded+permuted gate_w
__device__ float g_uw[(size_t)NEXP * FD * HD];   // rounded+permuted up_w
__device__ float g_dw[(size_t)NEXP * HD * FD];   // rounded+permuted down_w
__device__ float g_hbuf[(size_t)NTOK * 2 * FD];  // swiglu out (rounded+permuted)
__device__ float g_sout[(size_t)NTOK * 2 * HD];  // weighted down out per slot

// ---------------------------------------------------------------------------
// helpers
// ---------------------------------------------------------------------------
__device__ __forceinline__ uint32_t to_tf32(float f) {
  uint32_t u;
  asm("cvt.rna.tf32.f32 %0, %1;" : "=r"(u) : "f"(f));
  return u;
}
__device__ __forceinline__ float round_tf32(float f) {
  return __uint_as_float(to_tf32(f));
}

__device__ __forceinline__ void mma_tf32(float* c, const uint32_t* a, const uint32_t* b) {
  asm volatile(
      "mma.sync.aligned.m16n8k8.row.col.f32.tf32.tf32.f32 "
      "{%0,%1,%2,%3}, {%4,%5,%6,%7}, {%8,%9}, {%0,%1,%2,%3};\n"
      : "+f"(c[0]), "+f"(c[1]), "+f"(c[2]), "+f"(c[3])
      : "r"(a[0]), "r"(a[1]), "r"(a[2]), "r"(a[3]), "r"(b[0]), "r"(b[1]));
}

__device__ __forceinline__ void cp16(void* sdst, const void* gsrc, int src_bytes) {
  uint32_t sa = (uint32_t)__cvta_generic_to_shared(sdst);
  asm volatile("cp.async.cg.shared.global [%0], [%1], 16, %2;\n"
               :: "r"(sa), "l"(gsrc), "r"(src_bytes));
}
__device__ __forceinline__ void cp_commit() {
  asm volatile("cp.async.commit_group;\n");
}

// ---------------------------------------------------------------------------
// 0) zero expert counters
// ---------------------------------------------------------------------------
__global__ void zero_counts_kernel() {
  if (threadIdx.x < NEXP) g_count[threadIdx.x] = 0;
}

// ---------------------------------------------------------------------------
// 0b) rna-round to tf32 + k-pair permute: every 8-float group rewritten as
//     [k0,k4,k1,k5,k2,k6,k3,k7] so an mma fragment's (k, k+4) pair is one
//     contiguous 8-byte LDS.64 after cp.async.
// ---------------------------------------------------------------------------
__global__ void __launch_bounds__(256) round_perm_kernel(
    const float4* __restrict__ src, float4* __restrict__ dst, int n8) {
  int i = blockIdx.x * 256 + threadIdx.x;
  if (i >= n8) return;
  float4 v0 = src[2 * i], v1 = src[2 * i + 1];
  float4 o0, o1;
  o0.x = round_tf32(v0.x); o0.y = round_tf32(v1.x);
  o0.z = round_tf32(v0.y); o0.w = round_tf32(v1.y);
  o1.x = round_tf32(v0.z); o1.y = round_tf32(v1.z);
  o1.z = round_tf32(v0.w); o1.w = round_tf32(v1.w);
  dst[2 * i] = o0;
  dst[2 * i + 1] = o1;
}

// ---------------------------------------------------------------------------
// 1) router (exact fp32, raw x): top-2 softmax weights + slot assignment.
//    Atomic ordering only permutes rows within an expert; each row's math is
//    independent and scattered by slot id -> bit-deterministic output.
// ---------------------------------------------------------------------------
__global__ void __launch_bounds__(256) router_kernel(
    const float* __restrict__ x, const float* __restrict__ rw) {
  __shared__ float4 xs[HD / 4];
  __shared__ float logits[NEXP];
  const int t = blockIdx.x;
  const float4* xr = (const float4*)(x + (size_t)t * HD);
  for (int i = threadIdx.x; i < HD / 4; i += 256) xs[i] = xr[i];
  __syncthreads();
  const int w = threadIdx.x >> 5, lane = threadIdx.x & 31;
  const float4* rw4 = (const float4*)(rw + w * HD);
  float acc = 0.f;
  for (int i = lane; i < HD / 4; i += 32) {
    float4 a = xs[i], b = rw4[i];
    acc += a.x * b.x + a.y * b.y + a.z * b.z + a.w * b.w;
  }
  #pragma unroll
  for (int off = 16; off > 0; off >>= 1) acc += __shfl_xor_sync(0xffffffffu, acc, off);
  if (lane == 0) logits[w] = acc;
  __syncthreads();
  if (threadIdx.x == 0) {
    int e0 = 0; float l0 = logits[0];
    #pragma unroll
    for (int e = 1; e < NEXP; e++) if (logits[e] > l0) { l0 = logits[e]; e0 = e; }
    int e1 = -1; float l1 = -3.4e38f;
    #pragma unroll
    for (int e = 0; e < NEXP; e++) if (e != e0 && logits[e] > l1) { l1 = logits[e]; e1 = e; }
    float p1 = __expf(l1 - l0);      // l0 >= l1
    float inv = 1.f / (1.f + p1);
    int pos0 = atomicAdd(&g_count[e0], 1);
    g_slots[e0 * CAP + pos0] = 2 * t;
    g_slot_w[2 * t] = inv;
    int pos1 = atomicAdd(&g_count[e1], 1);
    g_slots[e1 * CAP + pos1] = 2 * t + 1;
    g_slot_w[2 * t + 1] = p1 * inv;
  }
}

// ---------------------------------------------------------------------------
// 2) fused gate+up GEMM + SwiGLU.  C[128 x 64] per block (dual-mat),
//    tf32 mma, LDS.64 paired fragment loads, NO in-loop cvt, NO reg cap.
// ---------------------------------------------------------------------------
__global__ void __launch_bounds__(256) gemm_gateup_kernel(
    const float* __restrict__ x,
    const float* __restrict__ gate_w,
    const float* __restrict__ up_w) {
  const int e = blockIdx.z;
  const int Ne = g_count[e];
  const int bm = blockIdx.y;
  if (bm * 128 >= Ne) return;
  const int bn = blockIdx.x;
  const int tid = threadIdx.x;

  extern __shared__ float sm[];
  int* slots = (int*)(sm + GU_SLOTS);

  if (tid < 128) {
    int gr = bm * 128 + tid;
    slots[tid] = (gr < Ne) ? g_slots[e * CAP + gr] : -1;
  }
  __syncthreads();

  // producer mapping
  const int ar = tid >> 1;                 // A row 0..127
  const int ah = (tid & 1) * 16;           // half-row (16 floats = 64B)
  const int s_a = slots[ar];
  const float* gA = x + (size_t)((s_a >= 0) ? (s_a >> 1) : 0) * HD + ah;
  const int a_sz = (s_a >= 0) ? 16 : 0;
  const int br = tid >> 2;                 // B row 0..63
  const int bq = (tid & 3) * 8;            // quarter-row (8 floats = 32B)
  const size_t wbase = (size_t)e * FD * HD;
  const float* gG = gate_w + wbase + (size_t)(bn * 64 + br) * HD + bq;
  const float* gU = up_w   + wbase + (size_t)(bn * 64 + br) * HD + bq;

  const int wid = tid >> 5, lane = tid & 31;
  const int wm = wid & 3, wn = wid >> 2;
  const int lr = lane >> 2, lc = lane & 3;

  float cg[2][4][4], cu[2][4][4];
  #pragma unroll
  for (int i = 0; i < 2; i++)
    #pragma unroll
    for (int j = 0; j < 4; j++)
      #pragma unroll
      for (int q = 0; q < 4; q++) { cg[i][j][q] = 0.f; cu[i][j][q] = 0.f; }

  auto load_stage = [&](int kt, int buf) {
    const int k0 = kt * 32;
    float* dA = sm + GU_A(buf) + ar * AS + ah;
    const float* sA = gA + k0;
    cp16(dA,      sA,      a_sz);
    cp16(dA + 4,  sA + 4,  a_sz);
    cp16(dA + 8,  sA + 8,  a_sz);
    cp16(dA + 12, sA + 12, a_sz);
    float* dG = sm + GU_G(buf) + br * AS + bq;
    float* dU = sm + GU_U(buf) + br * AS + bq;
    cp16(dG,     gG + k0,     16);
    cp16(dG + 4, gG + k0 + 4, 16);
    cp16(dU,     gU + k0,     16);
    cp16(dU + 4, gU + k0 + 4, 16);
    cp_commit();
  };

  auto compute_stage = [&](int buf) {
    const float* Ab = sm + GU_A(buf);
    const float* Gb = sm + GU_G(buf);
    const float* Ub = sm + GU_U(buf);
    #pragma unroll
    for (int ks = 0; ks < 4; ks++) {
      const int co = ks * 8 + lc * 2;      // permuted pair (k, k+4)
      uint32_t af[2][4];
      #pragma unroll
      for (int i = 0; i < 2; i++) {
        const int r = wm * 32 + i * 16 + lr;
        float2 lo = *(const float2*)(Ab + r * AS + co);
        float2 hi = *(const float2*)(Ab + (r + 8) * AS + co);
        af[i][0] = __float_as_uint(lo.x);
        af[i][1] = __float_as_uint(hi.x);
        af[i][2] = __float_as_uint(lo.y);
        af[i][3] = __float_as_uint(hi.y);
      }
      uint32_t bg[4][2], bu[4][2];
      #pragma unroll
      for (int j = 0; j < 4; j++) {
        const int n = wn * 32 + j * 8 + lr;
        float2 g = *(const float2*)(Gb + n * AS + co);
        float2 u = *(const float2*)(Ub + n * AS + co);
        bg[j][0] = __float_as_uint(g.x); bg[j][1] = __float_as_uint(g.y);
        bu[j][0] = __float_as_uint(u.x); bu[j][1] = __float_as_uint(u.y);
      }
      #pragma unroll
      for (int i = 0; i < 2; i++)
        #pragma unroll
        for (int j = 0; j < 4; j++) {
          mma_tf32(cg[i][j], af[i], bg[j]);
          mma_tf32(cu[i][j], af[i], bu[j]);
        }
    }
  };

  load_stage(0, 0);
  #pragma unroll 1
  for (int kt = 0; kt < KT1; kt++) {
    const int buf = kt & 1;
    if (kt + 1 < KT1) {
      load_stage(kt + 1, buf ^ 1);
      asm volatile("cp.async.wait_group 1;\n");
    } else {
      asm volatile("cp.async.wait_group 0;\n");
    }
    __syncthreads();
    compute_stage(buf);
    __syncthreads();
  }

  // SwiGLU epilogue -> hbuf[slot][F], stored ROUNDED + K-PERMUTED
  // cols (2lc, 2lc+1) land at permuted positions (pos0, pos0+2)
  const int pos0 = ((lc & 1) << 2) | (lc >> 1);    // 0,4,1,5
  #pragma unroll
  for (int i = 0; i < 2; i++)
    #pragma unroll
    for (int h = 0; h < 2; h++) {
      const int r = wm * 32 + i * 16 + h * 8 + lr;
      const int s = slots[r];
      if (s < 0) continue;
      float* orow = g_hbuf + (size_t)s * FD + bn * 64 + wn * 32;
      #pragma unroll
      for (int j = 0; j < 4; j++) {
        float g0 = cg[i][j][h * 2], g1 = cg[i][j][h * 2 + 1];
        float u0 = cu[i][j][h * 2], u1 = cu[i][j][h * 2 + 1];
        float v0 = g0 * u0 / (1.f + __expf(-g0));
        float v1 = g1 * u1 / (1.f + __expf(-g1));
        orow[j * 8 + pos0]     = round_tf32(v0);
        orow[j * 8 + pos0 + 2] = round_tf32(v1);
      }
    }
}

// ---------------------------------------------------------------------------
// 3) down GEMM: sout[slot][H] = weight * (hbuf[slot] @ down_w[e]^T)
//    CTA tile 128 x 64 (proven shape), LDS.64 paired loads, no cvt, no cap.
// ---------------------------------------------------------------------------
__global__ void __launch_bounds__(256) gemm_down_kernel(
    const float* __restrict__ down_w) {
  const int e = blockIdx.z;
  const int Ne = g_count[e];
  const int bm = blockIdx.y;
  if (bm * 128 >= Ne) return;
  const int bn = blockIdx.x;
  const int tid = threadIdx.x;

  extern __shared__ float sm[];
  int* slots = (int*)(sm + DN_SLOTS);
  float* wts = (float*)(slots + 128);

  if (tid < 128) {
    int gr = bm * 128 + tid;
    int s = (gr < Ne) ? g_slots[e * CAP + gr] : -1;
    slots[tid] = s;
    wts[tid] = (s >= 0) ? g_slot_w[s] : 0.f;
  }
  __syncthreads();

  const int ar = tid >> 1;
  const int ah = (tid & 1) * 16;
  const int s_a = slots[ar];
  const float* gA = g_hbuf + (size_t)((s_a >= 0) ? s_a : 0) * FD + ah;
  const int a_sz = (s_a >= 0) ? 16 : 0;
  const int br = tid >> 2;
  const int bq = (tid & 3) * 8;
  const size_t wbase = (size_t)e * HD * FD;
  const float* gB = down_w + wbase + (size_t)(bn * 64 + br) * FD + bq;

  const int wid = tid >> 5, lane = tid & 31;
  const int wm = wid & 3, wn = wid >> 2;
  const int lr = lane >> 2, lc = lane & 3;

  float cd[2][4][4];
  #pragma unroll
  for (int i = 0; i < 2; i++)
    #pragma unroll
    for (int j = 0; j < 4; j++)
      #pragma unroll
      for (int q = 0; q < 4; q++) cd[i][j][q] = 0.f;

  auto load_stage = [&](int kt, int buf) {
    const int k0 = kt * 32;
    float* dA = sm + DN_A(buf) + ar * AS + ah;
    const float* sA = gA + k0;
    cp16(dA,      sA,      a_sz);
    cp16(dA + 4,  sA + 4,  a_sz);
    cp16(dA + 8,  sA + 8,  a_sz);
    cp16(dA + 12, sA + 12, a_sz);
    float* dB = sm + DN_B(buf) + br * AS + bq;
    const float* sB = gB + k0;
    cp16(dB,     sB,     16);
    cp16(dB + 4, sB + 4, 16);
    cp_commit();
  };

  auto compute_stage = [&](int buf) {
    const float* Ab = sm + DN_A(buf);
    const float* Bb = sm + DN_B(buf);
    #pragma unroll
    for (int ks = 0; ks < 4; ks++) {
      const int co = ks * 8 + lc * 2;
      uint32_t af[2][4];
      #pragma unroll
      for (int i = 0; i < 2; i++) {
        const int r = wm * 32 + i * 16 + lr;
        float2 lo = *(const float2*)(Ab + r * AS + co);
        float2 hi = *(const float2*)(Ab + (r + 8) * AS + co);
        af[i][0] = __float_as_uint(lo.x);
        af[i][1] = __float_as_uint(hi.x);
        af[i][2] = __float_as_uint(lo.y);
        af[i][3] = __float_as_uint(hi.y);
      }
      uint32_t bd[4][2];
      #pragma unroll
      for (int j = 0; j < 4; j++) {
        const int n = wn * 32 + j * 8 + lr;
        float2 b = *(const float2*)(Bb + n * AS + co);
        bd[j][0] = __float_as_uint(b.x);
        bd[j][1] = __float_as_uint(b.y);
      }
      #pragma unroll
      for (int i = 0; i < 2; i++)
        #pragma unroll
        for (int j = 0; j < 4; j++)
          mma_tf32(cd[i][j], af[i], bd[j]);
    }
  };

  load_stage(0, 0);
  #pragma unroll 1
  for (int kt = 0; kt < KT2; kt++) {
    const int buf = kt & 1;
    if (kt + 1 < KT2) {
      load_stage(kt + 1, buf ^ 1);
      asm volatile("cp.async.wait_group 1;\n");
    } else {
      asm volatile("cp.async.wait_group 0;\n");
    }
    __syncthreads();
    compute_stage(buf);
    __syncthreads();
  }

  #pragma unroll
  for (int i = 0; i < 2; i++)
    #pragma unroll
    for (int h = 0; h < 2; h++) {
      const int r = wm * 32 + i * 16 + h * 8 + lr;
      const int s = slots[r];
      if (s < 0) continue;
      const float wgt = wts[r];
      float* orow = g_sout + (size_t)s * HD + bn * 64 + wn * 32 + lc * 2;
      #pragma unroll
      for (int j = 0; j < 4; j++) {
        float v0 = cd[i][j][h * 2] * wgt;
        float v1 = cd[i][j][h * 2 + 1] * wgt;
        *(float2*)(orow + j * 8) = make_float2(v0, v1);
      }
    }
}

// ---------------------------------------------------------------------------
// 4) deterministic combine: out[t] = sout[2t] + sout[2t+1]
// ---------------------------------------------------------------------------
__global__ void __launch_bounds__(256) combine_kernel(float* __restrict__ out) {
  const int idx = blockIdx.x * 256 + threadIdx.x;   // float4 index
  const int t = idx >> 9;                           // HD/4 = 512
  const int h4 = idx & 511;
  const float4* s4 = (const float4*)g_sout;
  float4 a = s4[(size_t)(2 * t) * 512 + h4];
  float4 b = s4[(size_t)(2 * t + 1) * 512 + h4];
  ((float4*)out)[idx] = make_float4(a.x + b.x, a.y + b.y, a.z + b.z, a.w + b.w);
}

// ---------------------------------------------------------------------------
extern "C" void kernel_launch(void* const* d_in, const int* in_sizes, int n_in,
                              void* d_out, int out_size) {
  const float* x  = (const float*)d_in[0];  // hidden_states [4,2048,2048]
  const float* rw = (const float*)d_in[1];  // router_w [8,2048]
  const float* gw = (const float*)d_in[2];  // gate_w [8,1408,2048]
  const float* uw = (const float*)d_in[3];  // up_w   [8,1408,2048]
  const float* dw = (const float*)d_in[4];  // down_w [8,2048,1408]
  float* out = (float*)d_out;

  cudaFuncSetAttribute(gemm_gateup_kernel,
                       cudaFuncAttributeMaxDynamicSharedMemorySize, SMEM_GU);
  cudaFuncSetAttribute(gemm_down_kernel,
                       cudaFuncAttributeMaxDynamicSharedMemorySize, SMEM_DN);

  float* xr_p;  cudaGetSymbolAddress((void**)&xr_p, g_xr);
  float* gw_p;  cudaGetSymbolAddress((void**)&gw_p, g_gw);
  float* uw_p;  cudaGetSymbolAddress((void**)&uw_p, g_uw);
  float* dw_p;  cudaGetSymbolAddress((void**)&dw_p, g_dw);

  const int n8x = NTOK * HD / 8;        // 2,097,152
  const int n8w = NEXP * FD * HD / 8;   // 2,883,584

  zero_counts_kernel<<<1, 32>>>();
  round_perm_kernel<<<(n8x + 255) / 256, 256>>>((const float4*)x,  (float4*)xr_p, n8x);
  round_perm_kernel<<<(n8w + 255) / 256, 256>>>((const float4*)gw, (float4*)gw_p, n8w);
  round_perm_kernel<<<(n8w + 255) / 256, 256>>>((const float4*)uw, (float4*)uw_p, n8w);
  round_perm_kernel<<<(n8w + 255) / 256, 256>>>((const float4*)dw, (float4*)dw_p, n8w);
  router_kernel<<<NTOK, 256>>>(x, rw);
  gemm_gateup_kernel<<<dim3(FD / 64, CAP / 128, NEXP), 256, SMEM_GU>>>(xr_p, gw_p, uw_p);
  gemm_down_kernel<<<dim3(HD / 64, CAP / 128, NEXP), 256, SMEM_DN>>>(dw_p);
  combine_kernel<<<(NTOK * (HD / 4)) / 256, 256>>>(out);
}

// round 17
// speedup vs baseline: 3.5449x; 2.2402x over previous
#include <cuda_runtime.h>
#include <cuda_fp16.h>
#include <cstdint>
#include <cstddef>

// Problem constants
#define NTOK 8192          // B*S tokens
#define HD   2048          // hidden
#define NEXP 8             // experts
#define FD   1408          // moe inter dim
#define CAP  8192          // per-expert row capacity

#define KT1  (HD / 32)     // 64 k-stages (32 halves each) for gate/up
#define KT2  (FD / 32)     // 44 k-stages for down

// smem geometry (fp16 units): stage row = 32 halfs (64B), XOR bank swizzle
#define ASTG  (128 * 32)   // 4096 halfs = 8 KB
#define BSTG  (64 * 32)    // 2048 halfs = 4 KB

// gateup smem (half units): A[2], G[2], U[2], then slots
#define GU_A(buf)  ((buf) * ASTG)
#define GU_G(buf)  (2 * ASTG + (buf) * BSTG)
#define GU_U(buf)  (2 * ASTG + 2 * BSTG + (buf) * BSTG)
#define GU_END     (2 * ASTG + 4 * BSTG)
#define SMEM_GU    (GU_END * 2 + 640)

// down smem: A[2], B[2], slots, wts
#define DN_A(buf)  ((buf) * ASTG)
#define DN_B(buf)  (2 * ASTG + (buf) * BSTG)
#define DN_END     (2 * ASTG + 2 * BSTG)
#define SMEM_DN    (DN_END * 2 + 1152)

// Scratch (device globals: allocation-free rule)
__device__ int    g_count[NEXP];
__device__ int    g_slots[NEXP * CAP];             // slot id = token*2 + k
__device__ float  g_slot_w[NTOK * 2];
__device__ __half g_xh[(size_t)NTOK * HD];         // fp16 + k-permuted x
__device__ __half g_gwh[(size_t)NEXP * FD * HD];   // fp16+perm gate_w
__device__ __half g_uwh[(size_t)NEXP * FD * HD];   // fp16+perm up_w
__device__ __half g_dwh[(size_t)NEXP * HD * FD];   // fp16+perm down_w
__device__ __half g_hbufh[(size_t)NTOK * 2 * FD];  // swiglu out (fp16+perm)
__device__ float  g_sout[(size_t)NTOK * 2 * HD];   // weighted down out per slot

// ---------------------------------------------------------------------------
// helpers
// ---------------------------------------------------------------------------
__device__ __forceinline__ uint32_t h2_as_u32(__half2 h) {
  union { __half2 h; uint32_t u; } cvt;
  cvt.h = h;
  return cvt.u;
}

__device__ __forceinline__ void mma_f16(float* c, const uint32_t* a, const uint32_t* b) {
  asm volatile(
      "mma.sync.aligned.m16n8k16.row.col.f32.f16.f16.f32 "
      "{%0,%1,%2,%3}, {%4,%5,%6,%7}, {%8,%9}, {%0,%1,%2,%3};\n"
      : "+f"(c[0]), "+f"(c[1]), "+f"(c[2]), "+f"(c[3])
      : "r"(a[0]), "r"(a[1]), "r"(a[2]), "r"(a[3]), "r"(b[0]), "r"(b[1]));
}

__device__ __forceinline__ void cp16(void* sdst, const void* gsrc, int src_bytes) {
  uint32_t sa = (uint32_t)__cvta_generic_to_shared(sdst);
  asm volatile("cp.async.cg.shared.global [%0], [%1], 16, %2;\n"
               :: "r"(sa), "l"(gsrc), "r"(src_bytes));
}
__device__ __forceinline__ void cp_commit() {
  asm volatile("cp.async.commit_group;\n");
}

// ---------------------------------------------------------------------------
// 0) zero expert counters
// ---------------------------------------------------------------------------
__global__ void zero_counts_kernel() {
  if (threadIdx.x < NEXP) g_count[threadIdx.x] = 0;
}

// ---------------------------------------------------------------------------
// 0b) fp32 -> fp16(rn) convert + 16-group k-permute:
//     out[4c+0]=in[2c]  out[4c+1]=in[2c+1]  out[4c+2]=in[2c+8]  out[4c+3]=in[2c+9]
//     => a thread's k16 mma fragment (2lc,2lc+1,2lc+8,2lc+9) is one LDS.64.
// ---------------------------------------------------------------------------
__global__ void __launch_bounds__(256) cvt_perm_kernel(
    const float4* __restrict__ src, uint2* __restrict__ dst, int n16) {
  int i = blockIdx.x * 256 + threadIdx.x;
  if (i >= n16) return;
  float4 f0 = src[4 * i + 0], f1 = src[4 * i + 1];
  float4 f2 = src[4 * i + 2], f3 = src[4 * i + 3];
  uint32_t h0 = h2_as_u32(__floats2half2_rn(f0.x, f0.y));
  uint32_t h1 = h2_as_u32(__floats2half2_rn(f2.x, f2.y));
  uint32_t h2 = h2_as_u32(__floats2half2_rn(f0.z, f0.w));
  uint32_t h3 = h2_as_u32(__floats2half2_rn(f2.z, f2.w));
  uint32_t h4 = h2_as_u32(__floats2half2_rn(f1.x, f1.y));
  uint32_t h5 = h2_as_u32(__floats2half2_rn(f3.x, f3.y));
  uint32_t h6 = h2_as_u32(__floats2half2_rn(f1.z, f1.w));
  uint32_t h7 = h2_as_u32(__floats2half2_rn(f3.z, f3.w));
  dst[4 * i + 0] = make_uint2(h0, h1);
  dst[4 * i + 1] = make_uint2(h2, h3);
  dst[4 * i + 2] = make_uint2(h4, h5);
  dst[4 * i + 3] = make_uint2(h6, h7);
}

// ---------------------------------------------------------------------------
// 1) router (exact fp32, raw x): top-2 softmax weights + slot assignment.
//    Atomic ordering only permutes rows within an expert; each row's math is
//    independent and scattered by slot id -> bit-deterministic output.
// ---------------------------------------------------------------------------
__global__ void __launch_bounds__(256) router_kernel(
    const float* __restrict__ x, const float* __restrict__ rw) {
  __shared__ float4 xs[HD / 4];
  __shared__ float logits[NEXP];
  const int t = blockIdx.x;
  const float4* xr = (const float4*)(x + (size_t)t * HD);
  for (int i = threadIdx.x; i < HD / 4; i += 256) xs[i] = xr[i];
  __syncthreads();
  const int w = threadIdx.x >> 5, lane = threadIdx.x & 31;
  const float4* rw4 = (const float4*)(rw + w * HD);
  float acc = 0.f;
  for (int i = lane; i < HD / 4; i += 32) {
    float4 a = xs[i], b = rw4[i];
    acc += a.x * b.x + a.y * b.y + a.z * b.z + a.w * b.w;
  }
  #pragma unroll
  for (int off = 16; off > 0; off >>= 1) acc += __shfl_xor_sync(0xffffffffu, acc, off);
  if (lane == 0) logits[w] = acc;
  __syncthreads();
  if (threadIdx.x == 0) {
    int e0 = 0; float l0 = logits[0];
    #pragma unroll
    for (int e = 1; e < NEXP; e++) if (logits[e] > l0) { l0 = logits[e]; e0 = e; }
    int e1 = -1; float l1 = -3.4e38f;
    #pragma unroll
    for (int e = 0; e < NEXP; e++) if (e != e0 && logits[e] > l1) { l1 = logits[e]; e1 = e; }
    float p1 = __expf(l1 - l0);      // l0 >= l1
    float inv = 1.f / (1.f + p1);
    int pos0 = atomicAdd(&g_count[e0], 1);
    g_slots[e0 * CAP + pos0] = 2 * t;
    g_slot_w[2 * t] = inv;
    int pos1 = atomicAdd(&g_count[e1], 1);
    g_slots[e1 * CAP + pos1] = 2 * t + 1;
    g_slot_w[2 * t + 1] = p1 * inv;
  }
}

// XOR swizzle for a row's column offset (half units, col in [0,32))
#define SWZ(row, col) ((col) ^ ((((row) >> 1) & 1) * 16))

// ---------------------------------------------------------------------------
// 2) fused gate+up GEMM + SwiGLU.  C[128 x 64] per block (dual-mat),
//    fp16 m16n8k16 mma (K=16/instr, half the HMMA count of tf32).
// ---------------------------------------------------------------------------
__global__ void __launch_bounds__(256) gemm_gateup_kernel(
    const __half* __restrict__ xh,
    const __half* __restrict__ gwh,
    const __half* __restrict__ uwh) {
  const int e = blockIdx.z;
  const int Ne = g_count[e];
  const int bm = blockIdx.y;
  if (bm * 128 >= Ne) return;
  const int bn = blockIdx.x;
  const int tid = threadIdx.x;

  extern __shared__ __half sm[];
  int* slots = (int*)(sm + GU_END);

  if (tid < 128) {
    int gr = bm * 128 + tid;
    slots[tid] = (gr < Ne) ? g_slots[e * CAP + gr] : -1;
  }
  __syncthreads();

  // producers: A thread -> row tid>>1, 16-half half-row (2 cp16s);
  //            B thread -> row tid>>2, 8-half chunk (1 cp16 each mat)
  const int ar = tid >> 1;
  const int aq0 = (tid & 1) * 2;          // chunk index 0..3 (8 halfs each)
  const int s_a = slots[ar];
  const __half* gA = xh + (size_t)((s_a >= 0) ? (s_a >> 1) : 0) * HD;
  const int a_sz = (s_a >= 0) ? 16 : 0;
  const int br = tid >> 2;
  const int bq = tid & 3;
  const size_t wbase = (size_t)e * FD * HD;
  const __half* gG = gwh + wbase + (size_t)(bn * 64 + br) * HD;
  const __half* gU = uwh + wbase + (size_t)(bn * 64 + br) * HD;

  const int wid = tid >> 5, lane = tid & 31;
  const int wm = wid & 3, wn = wid >> 2;
  const int lr = lane >> 2, lc = lane & 3;

  float cg[2][4][4], cu[2][4][4];
  #pragma unroll
  for (int i = 0; i < 2; i++)
    #pragma unroll
    for (int j = 0; j < 4; j++)
      #pragma unroll
      for (int q = 0; q < 4; q++) { cg[i][j][q] = 0.f; cu[i][j][q] = 0.f; }

  auto load_stage = [&](int kt, int buf) {
    const int k0 = kt * 32;
    __half* Ab = sm + GU_A(buf);
    #pragma unroll
    for (int q2 = 0; q2 < 2; q2++) {
      int q = aq0 + q2;
      cp16(Ab + ar * 32 + SWZ(ar, 8 * q), gA + k0 + 8 * q, a_sz);
    }
    cp16(sm + GU_G(buf) + br * 32 + SWZ(br, 8 * bq), gG + k0 + 8 * bq, 16);
    cp16(sm + GU_U(buf) + br * 32 + SWZ(br, 8 * bq), gU + k0 + 8 * bq, 16);
    cp_commit();
  };

  auto compute_stage = [&](int buf) {
    const __half* Ab = sm + GU_A(buf);
    const __half* Gb = sm + GU_G(buf);
    const __half* Ub = sm + GU_U(buf);
    #pragma unroll
    for (int ks = 0; ks < 2; ks++) {          // two k16 steps per 32-k stage
      const int co = ks * 16 + lc * 4;        // permuted fragment offset
      uint32_t af[2][4];
      #pragma unroll
      for (int i = 0; i < 2; i++) {
        const int r = wm * 32 + i * 16 + lr;
        uint2 lo = *(const uint2*)(Ab + r * 32 + SWZ(r, co));
        uint2 hi = *(const uint2*)(Ab + (r + 8) * 32 + SWZ(r + 8, co));
        af[i][0] = lo.x; af[i][1] = hi.x; af[i][2] = lo.y; af[i][3] = hi.y;
      }
      uint32_t bg[4][2], bu[4][2];
      #pragma unroll
      for (int j = 0; j < 4; j++) {
        const int n = wn * 32 + j * 8 + lr;
        uint2 g = *(const uint2*)(Gb + n * 32 + SWZ(n, co));
        uint2 u = *(const uint2*)(Ub + n * 32 + SWZ(n, co));
        bg[j][0] = g.x; bg[j][1] = g.y;
        bu[j][0] = u.x; bu[j][1] = u.y;
      }
      #pragma unroll
      for (int i = 0; i < 2; i++)
        #pragma unroll
        for (int j = 0; j < 4; j++) {
          mma_f16(cg[i][j], af[i], bg[j]);
          mma_f16(cu[i][j], af[i], bu[j]);
        }
    }
  };

  load_stage(0, 0);
  #pragma unroll 1
  for (int kt = 0; kt < KT1; kt++) {
    const int buf = kt & 1;
    if (kt + 1 < KT1) {
      load_stage(kt + 1, buf ^ 1);
      asm volatile("cp.async.wait_group 1;\n");
    } else {
      asm volatile("cp.async.wait_group 0;\n");
    }
    __syncthreads();
    compute_stage(buf);
    __syncthreads();
  }

  // SwiGLU epilogue -> hbuf[slot][F] stored fp16 + k-permuted.
  // col v = 8*(j&1) + 2lc + d within its 16-group maps to pos 4lc+2(j&1)+d
  // (pair contiguous -> one half2 store).
  #pragma unroll
  for (int i = 0; i < 2; i++)
    #pragma unroll
    for (int h = 0; h < 2; h++) {
      const int r = wm * 32 + i * 16 + h * 8 + lr;
      const int s = slots[r];
      if (s < 0) continue;
      __half* orow = g_hbufh + (size_t)s * FD + bn * 64 + wn * 32;
      #pragma unroll
      for (int j = 0; j < 4; j++) {
        float g0 = cg[i][j][h * 2], g1 = cg[i][j][h * 2 + 1];
        float u0 = cu[i][j][h * 2], u1 = cu[i][j][h * 2 + 1];
        float v0 = g0 * u0 / (1.f + __expf(-g0));
        float v1 = g1 * u1 / (1.f + __expf(-g1));
        int off = (j >> 1) * 16 + 4 * lc + 2 * (j & 1);
        *(__half2*)(orow + off) = __floats2half2_rn(v0, v1);
      }
    }
}

// ---------------------------------------------------------------------------
// 3) down GEMM: sout[slot][H] = weight * (hbuf[slot] @ down_w[e]^T)
//    CTA tile 128 x 64, fp16 m16n8k16.
// ---------------------------------------------------------------------------
__global__ void __launch_bounds__(256) gemm_down_kernel(
    const __half* __restrict__ dwh) {
  const int e = blockIdx.z;
  const int Ne = g_count[e];
  const int bm = blockIdx.y;
  if (bm * 128 >= Ne) return;
  const int bn = blockIdx.x;
  const int tid = threadIdx.x;

  extern __shared__ __half sm[];
  int* slots = (int*)(sm + DN_END);
  float* wts = (float*)(slots + 128);

  if (tid < 128) {
    int gr = bm * 128 + tid;
    int s = (gr < Ne) ? g_slots[e * CAP + gr] : -1;
    slots[tid] = s;
    wts[tid] = (s >= 0) ? g_slot_w[s] : 0.f;
  }
  __syncthreads();

  const int ar = tid >> 1;
  const int aq0 = (tid & 1) * 2;
  const int s_a = slots[ar];
  const __half* gA = g_hbufh + (size_t)((s_a >= 0) ? s_a : 0) * FD;
  const int a_sz = (s_a >= 0) ? 16 : 0;
  const int br = tid >> 2;
  const int bq = tid & 3;
  const size_t wbase = (size_t)e * HD * FD;
  const __half* gB = dwh + wbase + (size_t)(bn * 64 + br) * FD;

  const int wid = tid >> 5, lane = tid & 31;
  const int wm = wid & 3, wn = wid >> 2;
  const int lr = lane >> 2, lc = lane & 3;

  float cd[2][4][4];
  #pragma unroll
  for (int i = 0; i < 2; i++)
    #pragma unroll
    for (int j = 0; j < 4; j++)
      #pragma unroll
      for (int q = 0; q < 4; q++) cd[i][j][q] = 0.f;

  auto load_stage = [&](int kt, int buf) {
    const int k0 = kt * 32;
    __half* Ab = sm + DN_A(buf);
    #pragma unroll
    for (int q2 = 0; q2 < 2; q2++) {
      int q = aq0 + q2;
      cp16(Ab + ar * 32 + SWZ(ar, 8 * q), gA + k0 + 8 * q, a_sz);
    }
    cp16(sm + DN_B(buf) + br * 32 + SWZ(br, 8 * bq), gB + k0 + 8 * bq, 16);
    cp_commit();
  };

  auto compute_stage = [&](int buf) {
    const __half* Ab = sm + DN_A(buf);
    const __half* Bb = sm + DN_B(buf);
    #pragma unroll
    for (int ks = 0; ks < 2; ks++) {
      const int co = ks * 16 + lc * 4;
      uint32_t af[2][4];
      #pragma unroll
      for (int i = 0; i < 2; i++) {
        const int r = wm * 32 + i * 16 + lr;
        uint2 lo = *(const uint2*)(Ab + r * 32 + SWZ(r, co));
        uint2 hi = *(const uint2*)(Ab + (r + 8) * 32 + SWZ(r + 8, co));
        af[i][0] = lo.x; af[i][1] = hi.x; af[i][2] = lo.y; af[i][3] = hi.y;
      }
      uint32_t bd[4][2];
      #pragma unroll
      for (int j = 0; j < 4; j++) {
        const int n = wn * 32 + j * 8 + lr;
        uint2 b = *(const uint2*)(Bb + n * 32 + SWZ(n, co));
        bd[j][0] = b.x; bd[j][1] = b.y;
      }
      #pragma unroll
      for (int i = 0; i < 2; i++)
        #pragma unroll
        for (int j = 0; j < 4; j++)
          mma_f16(cd[i][j], af[i], bd[j]);
    }
  };

  load_stage(0, 0);
  #pragma unroll 1
  for (int kt = 0; kt < KT2; kt++) {
    const int buf = kt & 1;
    if (kt + 1 < KT2) {
      load_stage(kt + 1, buf ^ 1);
      asm volatile("cp.async.wait_group 1;\n");
    } else {
      asm volatile("cp.async.wait_group 0;\n");
    }
    __syncthreads();
    compute_stage(buf);
    __syncthreads();
  }

  #pragma unroll
  for (int i = 0; i < 2; i++)
    #pragma unroll
    for (int h = 0; h < 2; h++) {
      const int r = wm * 32 + i * 16 + h * 8 + lr;
      const int s = slots[r];
      if (s < 0) continue;
      const float wgt = wts[r];
      float* orow = g_sout + (size_t)s * HD + bn * 64 + wn * 32 + lc * 2;
      #pragma unroll
      for (int j = 0; j < 4; j++) {
        float v0 = cd[i][j][h * 2] * wgt;
        float v1 = cd[i][j][h * 2 + 1] * wgt;
        *(float2*)(orow + j * 8) = make_float2(v0, v1);
      }
    }
}

// ---------------------------------------------------------------------------
// 4) deterministic combine: out[t] = sout[2t] + sout[2t+1]
// ---------------------------------------------------------------------------
__global__ void __launch_bounds__(256) combine_kernel(float* __restrict__ out) {
  const int idx = blockIdx.x * 256 + threadIdx.x;   // float4 index
  const int t = idx >> 9;                           // HD/4 = 512
  const int h4 = idx & 511;
  const float4* s4 = (const float4*)g_sout;
  float4 a = s4[(size_t)(2 * t) * 512 + h4];
  float4 b = s4[(size_t)(2 * t + 1) * 512 + h4];
  ((float4*)out)[idx] = make_float4(a.x + b.x, a.y + b.y, a.z + b.z, a.w + b.w);
}

// ---------------------------------------------------------------------------
extern "C" void kernel_launch(void* const* d_in, const int* in_sizes, int n_in,
                              void* d_out, int out_size) {
  const float* x  = (const float*)d_in[0];  // hidden_states [4,2048,2048]
  const float* rw = (const float*)d_in[1];  // router_w [8,2048]
  const float* gw = (const float*)d_in[2];  // gate_w [8,1408,2048]
  const float* uw = (const float*)d_in[3];  // up_w   [8,1408,2048]
  const float* dw = (const float*)d_in[4];  // down_w [8,2048,1408]
  float* out = (float*)d_out;

  cudaFuncSetAttribute(gemm_gateup_kernel,
                       cudaFuncAttributeMaxDynamicSharedMemorySize, SMEM_GU);
  cudaFuncSetAttribute(gemm_down_kernel,
                       cudaFuncAttributeMaxDynamicSharedMemorySize, SMEM_DN);

  __half* xh_p;  cudaGetSymbolAddress((void**)&xh_p, g_xh);
  __half* gw_p;  cudaGetSymbolAddress((void**)&gw_p, g_gwh);
  __half* uw_p;  cudaGetSymbolAddress((void**)&uw_p, g_uwh);
  __half* dw_p;  cudaGetSymbolAddress((void**)&dw_p, g_dwh);

  const int n16x = NTOK * HD / 16;        // 1,048,576
  const int n16w = NEXP * FD * HD / 16;   // 1,441,792

  zero_counts_kernel<<<1, 32>>>();
  cvt_perm_kernel<<<(n16x + 255) / 256, 256>>>((const float4*)x,  (uint2*)xh_p, n16x);
  cvt_perm_kernel<<<(n16w + 255) / 256, 256>>>((const float4*)gw, (uint2*)gw_p, n16w);
  cvt_perm_kernel<<<(n16w + 255) / 256, 256>>>((const float4*)uw, (uint2*)uw_p, n16w);
  cvt_perm_kernel<<<(n16w + 255) / 256, 256>>>((const float4*)dw, (uint2*)dw_p, n16w);
  router_kernel<<<NTOK, 256>>>(x, rw);
  gemm_gateup_kernel<<<dim3(FD / 64, CAP / 128, NEXP), 256, SMEM_GU>>>(xh_p, gw_p, uw_p);
  gemm_down_kernel<<<dim3(HD / 64, CAP / 128, NEXP), 256, SMEM_DN>>>(dw_p);
  combine_kernel<<<(NTOK * (HD / 4)) / 256, 256>>>(out);
}